// round 1
// baseline (speedup 1.0000x reference)
#include <cuda_runtime.h>
#include <cuda_bf16.h>
#include <math.h>

// Problem constants
#define NB 4
#define LSEQ 256
#define MMEM 2
#define DDIM 768
#define HNUM 12
#define FFDIM 3072
#define LAYERS 4
#define TTOT 1032          // NB*MMEM + NB*LSEQ = 8 + 1024
#define KKEYS 258          // MMEM + LSEQ

// -------- scratch (device globals: no allocation allowed) --------
__device__ float g_x[TTOT * DDIM];
__device__ float g_q[TTOT * DDIM];
__device__ float g_k[TTOT * DDIM];
__device__ float g_v[TTOT * DDIM];
__device__ float g_ctx[TTOT * DDIM];
__device__ float g_h[TTOT * FFDIM];

// -------- embedding: x = concat(memory + pos, emb[ids] + pos) --------
__global__ void embed_kernel(const int* __restrict__ ids,
                             const float* __restrict__ memory,
                             const float* __restrict__ emb,
                             const float* __restrict__ pos,
                             float* __restrict__ x)
{
    int idx = blockIdx.x * blockDim.x + threadIdx.x;
    if (idx >= TTOT * DDIM) return;
    int t = idx / DDIM;
    int d = idx - t * DDIM;
    float val;
    if (t < NB * MMEM) {
        val = memory[idx] + pos[(t & 1) * DDIM + d];
    } else {
        int tt = t - NB * MMEM;
        int tok = ids[tt];
        val = emb[(size_t)tok * DDIM + d] + pos[(MMEM + (tt & (LSEQ - 1))) * DDIM + d];
    }
    x[idx] = val;
}

// -------- GEMM: C[M,N] = A[M,K] @ B[K,N] + bias, optional exact GELU --------
// BM=128, BN=64, BK=16, 256 threads, 8x4 microtile per thread.
__global__ __launch_bounds__(256)
void gemm_kernel(const float* __restrict__ A, const float* __restrict__ B,
                 const float* __restrict__ bias, float* __restrict__ C,
                 int Mr, int K, int Nc, int act)
{
    __shared__ float As[16][132];   // [k][m], padded
    __shared__ float Bs[16][68];    // [k][n], padded

    int tid = threadIdx.x;
    int tx = tid & 15;        // 0..15
    int ty = tid >> 4;        // 0..15
    int row0 = blockIdx.y * 128;
    int col0 = blockIdx.x * 64;

    float acc[8][4];
    #pragma unroll
    for (int i = 0; i < 8; i++)
        #pragma unroll
        for (int j = 0; j < 4; j++) acc[i][j] = 0.f;

    for (int k0 = 0; k0 < K; k0 += 16) {
        // load A tile (128x16): thread loads 8 elems, coalesced over k within row
        #pragma unroll
        for (int i = 0; i < 8; i++) {
            int m = ty + i * 16;
            int gm = row0 + m;
            As[tx][m] = (gm < Mr) ? A[(size_t)gm * K + k0 + tx] : 0.f;
        }
        // load B tile (16x64): thread loads 4 elems, coalesced over n
        #pragma unroll
        for (int i = 0; i < 4; i++) {
            int kk = (tid >> 6) + i * 4;
            int nn = tid & 63;
            Bs[kk][nn] = B[(size_t)(k0 + kk) * Nc + col0 + nn];
        }
        __syncthreads();
        #pragma unroll
        for (int kk = 0; kk < 16; kk++) {
            float bv[4];
            #pragma unroll
            for (int j = 0; j < 4; j++) bv[j] = Bs[kk][tx * 4 + j];
            #pragma unroll
            for (int i = 0; i < 8; i++) {
                float av = As[kk][ty * 8 + i];
                #pragma unroll
                for (int j = 0; j < 4; j++) acc[i][j] += av * bv[j];
            }
        }
        __syncthreads();
    }

    #pragma unroll
    for (int i = 0; i < 8; i++) {
        int gm = row0 + ty * 8 + i;
        if (gm >= Mr) continue;
        #pragma unroll
        for (int j = 0; j < 4; j++) {
            int gn = col0 + tx * 4 + j;
            float vv = acc[i][j] + bias[gn];
            if (act == 1)
                vv = 0.5f * vv * (1.f + erff(vv * 0.70710678118654752f));
            C[(size_t)gm * Nc + gn] = vv;
        }
    }
}

// -------- attention: one warp per (token, head); 4 heads per block --------
__global__ __launch_bounds__(128)
void attn_kernel(const float* __restrict__ q, const float* __restrict__ k,
                 const float* __restrict__ v, float* __restrict__ ctx)
{
    int t = blockIdx.x;
    int w = threadIdx.x >> 5;
    int lane = threadIdx.x & 31;
    int head = blockIdx.y * 4 + w;

    __shared__ float sc[4][264];
    __shared__ float qs[4][64];

    int b = (t < 8) ? (t >> 1) : ((t - 8) >> 8);
    const float scale = 0.125f;   // 1/sqrt(64)

    size_t qoff = (size_t)t * DDIM + head * 64;
    qs[w][lane]      = q[qoff + lane];
    qs[w][lane + 32] = q[qoff + lane + 32];
    __syncwarp();

    // pass 1: scores + running max (lanes strided over keys)
    float mx = -1e30f;
    for (int j = lane; j < KKEYS; j += 32) {
        int key = (j < MMEM) ? (2 * b + j) : (8 + b * LSEQ + j - MMEM);
        const float4* kp = (const float4*)(k + (size_t)key * DDIM + head * 64);
        float d = 0.f;
        #pragma unroll
        for (int i = 0; i < 16; i++) {
            float4 kv = kp[i];
            d += kv.x * qs[w][4*i] + kv.y * qs[w][4*i+1]
               + kv.z * qs[w][4*i+2] + kv.w * qs[w][4*i+3];
        }
        d *= scale;
        sc[w][j] = d;
        mx = fmaxf(mx, d);
    }
    #pragma unroll
    for (int o = 16; o > 0; o >>= 1)
        mx = fmaxf(mx, __shfl_xor_sync(0xffffffffu, mx, o));

    float lsum = 0.f;
    for (int j = lane; j < KKEYS; j += 32) {
        float e = __expf(sc[w][j] - mx);
        sc[w][j] = e;
        lsum += e;
    }
    #pragma unroll
    for (int o = 16; o > 0; o >>= 1)
        lsum += __shfl_xor_sync(0xffffffffu, lsum, o);
    float inv = 1.f / lsum;
    __syncwarp();

    // pass 2: ctx = probs @ V (lanes over dims, coalesced V reads)
    float a0 = 0.f, a1 = 0.f;
    for (int j = 0; j < KKEYS; j++) {
        int key = (j < MMEM) ? (2 * b + j) : (8 + b * LSEQ + j - MMEM);
        float p = sc[w][j];
        const float* vp = v + (size_t)key * DDIM + head * 64;
        a0 += p * vp[lane];
        a1 += p * vp[lane + 32];
    }
    ctx[qoff + lane]      = a0 * inv;
    ctx[qoff + lane + 32] = a1 * inv;
}

// -------- fused residual add + layernorm (in-place on x) --------
__global__ __launch_bounds__(256)
void add_ln_kernel(float* __restrict__ x, const float* __restrict__ r,
                   const float* __restrict__ g, const float* __restrict__ b)
{
    int t = blockIdx.x;
    int tid = threadIdx.x;
    __shared__ float red[256];
    __shared__ float s_mu, s_rstd;

    float v[3];
    float lsum = 0.f;
    #pragma unroll
    for (int i = 0; i < 3; i++) {
        int d = tid + i * 256;
        v[i] = x[(size_t)t * DDIM + d] + r[(size_t)t * DDIM + d];
        lsum += v[i];
    }
    red[tid] = lsum;
    __syncthreads();
    for (int s = 128; s > 0; s >>= 1) {
        if (tid < s) red[tid] += red[tid + s];
        __syncthreads();
    }
    if (tid == 0) s_mu = red[0] * (1.f / DDIM);
    __syncthreads();
    float mu = s_mu;

    float lvar = 0.f;
    #pragma unroll
    for (int i = 0; i < 3; i++) {
        float d = v[i] - mu;
        lvar += d * d;
    }
    red[tid] = lvar;
    __syncthreads();
    for (int s = 128; s > 0; s >>= 1) {
        if (tid < s) red[tid] += red[tid + s];
        __syncthreads();
    }
    if (tid == 0) s_rstd = rsqrtf(red[0] * (1.f / DDIM) + 1e-5f);
    __syncthreads();
    float rstd = s_rstd;

    #pragma unroll
    for (int i = 0; i < 3; i++) {
        int d = tid + i * 256;
        x[(size_t)t * DDIM + d] = (v[i] - mu) * rstd * g[d] + b[d];
    }
}

// -------- output: out = x[8:] (contiguous rows) --------
__global__ void copy_out_kernel(const float* __restrict__ x, float* __restrict__ out)
{
    int idx = blockIdx.x * blockDim.x + threadIdx.x;
    if (idx < NB * LSEQ * DDIM)
        out[idx] = x[NB * MMEM * DDIM + idx];
}

extern "C" void kernel_launch(void* const* d_in, const int* in_sizes, int n_in,
                              void* d_out, int out_size)
{
    const int*   ids    = (const int*)  d_in[0];
    const float* memory = (const float*)d_in[1];
    const float* emb    = (const float*)d_in[2];
    const float* pos    = (const float*)d_in[3];
    const float* Wq     = (const float*)d_in[4];
    const float* bq     = (const float*)d_in[5];
    const float* Wk     = (const float*)d_in[6];
    const float* bk     = (const float*)d_in[7];
    const float* Wv     = (const float*)d_in[8];
    const float* bv     = (const float*)d_in[9];
    const float* W1     = (const float*)d_in[10];
    const float* b1     = (const float*)d_in[11];
    const float* W2     = (const float*)d_in[12];
    const float* b2     = (const float*)d_in[13];
    const float* g1     = (const float*)d_in[14];
    const float* be1    = (const float*)d_in[15];
    const float* g2     = (const float*)d_in[16];
    const float* be2    = (const float*)d_in[17];
    float* out = (float*)d_out;

    float *x, *q, *k, *v, *ctx, *h;
    cudaGetSymbolAddress((void**)&x,   g_x);
    cudaGetSymbolAddress((void**)&q,   g_q);
    cudaGetSymbolAddress((void**)&k,   g_k);
    cudaGetSymbolAddress((void**)&v,   g_v);
    cudaGetSymbolAddress((void**)&ctx, g_ctx);
    cudaGetSymbolAddress((void**)&h,   g_h);

    embed_kernel<<<(TTOT * DDIM + 255) / 256, 256>>>(ids, memory, emb, pos, x);

    dim3 gemm_qkv(DDIM / 64, (TTOT + 127) / 128);   // (12, 9)
    dim3 gemm_ff1(FFDIM / 64, (TTOT + 127) / 128);  // (48, 9)
    dim3 gemm_ff2(DDIM / 64, (TTOT + 127) / 128);   // (12, 9)

    for (int i = 0; i < LAYERS; i++) {
        const float* wq = Wq + (size_t)i * DDIM * DDIM;
        const float* wk = Wk + (size_t)i * DDIM * DDIM;
        const float* wv = Wv + (size_t)i * DDIM * DDIM;
        gemm_kernel<<<gemm_qkv, 256>>>(x, wq, bq + i * DDIM, q, TTOT, DDIM, DDIM, 0);
        gemm_kernel<<<gemm_qkv, 256>>>(x, wk, bk + i * DDIM, k, TTOT, DDIM, DDIM, 0);
        gemm_kernel<<<gemm_qkv, 256>>>(x, wv, bv + i * DDIM, v, TTOT, DDIM, DDIM, 0);

        attn_kernel<<<dim3(TTOT, HNUM / 4), 128>>>(q, k, v, ctx);

        add_ln_kernel<<<TTOT, 256>>>(x, ctx, g1 + i * DDIM, be1 + i * DDIM);

        gemm_kernel<<<gemm_ff1, 256>>>(x, W1 + (size_t)i * DDIM * FFDIM,
                                       b1 + i * FFDIM, h, TTOT, DDIM, FFDIM, 1);
        gemm_kernel<<<gemm_ff2, 256>>>(h, W2 + (size_t)i * FFDIM * DDIM,
                                       b2 + i * DDIM, ctx, TTOT, FFDIM, DDIM, 0);

        add_ln_kernel<<<TTOT, 256>>>(x, ctx, g2 + i * DDIM, be2 + i * DDIM);
    }

    copy_out_kernel<<<(NB * LSEQ * DDIM + 255) / 256, 256>>>(x, out);
}

// round 4
// speedup vs baseline: 1.9436x; 1.9436x over previous
#include <cuda_runtime.h>
#include <cuda_bf16.h>
#include <math.h>
#include <stdint.h>

// Problem constants
#define NB 4
#define LSEQ 256
#define MMEM 2
#define DDIM 768
#define HNUM 12
#define FFDIM 3072
#define LAYERS 4
#define TTOT 1032          // NB*MMEM + NB*LSEQ
#define KKEYS 258          // MMEM + LSEQ

// -------- scratch (device globals: no allocation allowed) --------
__device__ float g_x[TTOT * DDIM];
__device__ float g_q[TTOT * DDIM];
__device__ float g_k[TTOT * DDIM];
__device__ float g_v[TTOT * DDIM];
__device__ float g_ctx[TTOT * DDIM];
__device__ float g_h[TTOT * FFDIM];

// ================= embedding =================
__global__ void embed_kernel(const int* __restrict__ ids,
                             const float* __restrict__ memory,
                             const float* __restrict__ emb,
                             const float* __restrict__ pos,
                             float* __restrict__ x)
{
    int idx = blockIdx.x * blockDim.x + threadIdx.x;
    if (idx >= TTOT * DDIM) return;
    int t = idx / DDIM;
    int d = idx - t * DDIM;
    float val;
    if (t < NB * MMEM) {
        val = memory[idx] + pos[(t & 1) * DDIM + d];
    } else {
        int tt = t - NB * MMEM;
        int tok = ids[tt];
        val = emb[(size_t)tok * DDIM + d] + pos[(MMEM + (tt & (LSEQ - 1))) * DDIM + d];
    }
    x[idx] = val;
}

// ================= bf16x3 tensor-core GEMM =================
// Tile: BM=64, BN=64, BK=32. 128 threads = 4 warps (2x2), warptile 32x32.
// C = A@B + bias, A[M,K], B[K,N] row-major fp32.
// Split: A=Ah+Al, B=Bh+Bl (bf16); acc += Ah*Bh + Ah*Bl + Al*Bh (fp32 acc).

#define SA 40   // A smem row stride (bf16 elems), 80B
#define SB 72   // B smem row stride (bf16 elems), 144B

struct __align__(16) GemmSmem {
    __nv_bfloat16 Ah[64 * SA];
    __nv_bfloat16 Al[64 * SA];
    __nv_bfloat16 Bh[32 * SB];
    __nv_bfloat16 Bl[32 * SB];
};

__device__ __forceinline__ void ldsm_x4(uint32_t* r, uint32_t addr) {
    asm volatile("ldmatrix.sync.aligned.m8n8.x4.shared.b16 {%0,%1,%2,%3}, [%4];\n"
        : "=r"(r[0]), "=r"(r[1]), "=r"(r[2]), "=r"(r[3]) : "r"(addr));
}
__device__ __forceinline__ void ldsm_x4_t(uint32_t* r, uint32_t addr) {
    asm volatile("ldmatrix.sync.aligned.m8n8.x4.trans.shared.b16 {%0,%1,%2,%3}, [%4];\n"
        : "=r"(r[0]), "=r"(r[1]), "=r"(r[2]), "=r"(r[3]) : "r"(addr));
}
__device__ __forceinline__ void mma_bf16(float* c, const uint32_t* a, const uint32_t* b) {
    asm volatile("mma.sync.aligned.m16n8k16.row.col.f32.bf16.bf16.f32 "
        "{%0,%1,%2,%3}, {%4,%5,%6,%7}, {%8,%9}, {%0,%1,%2,%3};\n"
        : "+f"(c[0]), "+f"(c[1]), "+f"(c[2]), "+f"(c[3])
        : "r"(a[0]), "r"(a[1]), "r"(a[2]), "r"(a[3]), "r"(b[0]), "r"(b[1]));
}

__device__ __forceinline__ uint32_t packbf(__nv_bfloat16 a, __nv_bfloat16 b) {
    __nv_bfloat162 t = __nv_bfloat162(a, b);
    return *reinterpret_cast<uint32_t*>(&t);
}

__device__ __forceinline__ void split4(float4 v, uint2& hi, uint2& lo) {
    __nv_bfloat16 h0 = __float2bfloat16(v.x);
    __nv_bfloat16 h1 = __float2bfloat16(v.y);
    __nv_bfloat16 h2 = __float2bfloat16(v.z);
    __nv_bfloat16 h3 = __float2bfloat16(v.w);
    __nv_bfloat16 l0 = __float2bfloat16(v.x - __bfloat162float(h0));
    __nv_bfloat16 l1 = __float2bfloat16(v.y - __bfloat162float(h1));
    __nv_bfloat16 l2 = __float2bfloat16(v.z - __bfloat162float(h2));
    __nv_bfloat16 l3 = __float2bfloat16(v.w - __bfloat162float(h3));
    hi.x = packbf(h0, h1); hi.y = packbf(h2, h3);
    lo.x = packbf(l0, l1); lo.y = packbf(l2, l3);
}

__device__ __forceinline__ void gemm_core(
    const float* __restrict__ A, const float* __restrict__ B,
    const float* __restrict__ bias, float* __restrict__ C,
    int Mr, int K, int Nc, int act, int row0, int col0)
{
    __shared__ GemmSmem s;

    int tid = threadIdx.x;
    int lane = tid & 31;
    int wid = tid >> 5;
    int wm = wid >> 1;          // 0..1
    int wn = wid & 1;           // 0..1

    float acc[2][4][4];
    #pragma unroll
    for (int im = 0; im < 2; im++)
        #pragma unroll
        for (int in = 0; in < 4; in++)
            #pragma unroll
            for (int r = 0; r < 4; r++) acc[im][in][r] = 0.f;

    int a_m = tid >> 3;          // 0..15
    int a_k4 = tid & 7;          // float4 within 32 cols
    int b_k = tid >> 4;          // 0..7
    int b_n4 = tid & 15;         // float4 within 64 cols

    // precompute ldmatrix shared addresses (base parts)
    int lrow = lane & 15;
    int lcol8 = (lane >> 4) * 8;

    for (int k0 = 0; k0 < K; k0 += 32) {
        // ---- load A 64x32 ----
        #pragma unroll
        for (int i = 0; i < 4; i++) {
            int m = a_m + i * 16;
            int gm = row0 + m;
            float4 av = (gm < Mr) ? *(const float4*)&A[(size_t)gm * K + k0 + a_k4 * 4]
                                  : make_float4(0.f, 0.f, 0.f, 0.f);
            uint2 hi, lo;
            split4(av, hi, lo);
            *(uint2*)&s.Ah[m * SA + a_k4 * 4] = hi;
            *(uint2*)&s.Al[m * SA + a_k4 * 4] = lo;
        }
        // ---- load B 32x64 ----
        #pragma unroll
        for (int i = 0; i < 4; i++) {
            int kk = b_k + i * 8;
            float4 bv = *(const float4*)&B[(size_t)(k0 + kk) * Nc + col0 + b_n4 * 4];
            uint2 hi, lo;
            split4(bv, hi, lo);
            *(uint2*)&s.Bh[kk * SB + b_n4 * 4] = hi;
            *(uint2*)&s.Bl[kk * SB + b_n4 * 4] = lo;
        }
        __syncthreads();

        #pragma unroll
        for (int ks = 0; ks < 32; ks += 16) {
            uint32_t ah[2][4], al[2][4];
            #pragma unroll
            for (int im = 0; im < 2; im++) {
                int mrow = wm * 32 + im * 16 + lrow;
                int mcol = ks + lcol8;
                ldsm_x4(ah[im], (uint32_t)__cvta_generic_to_shared(&s.Ah[mrow * SA + mcol]));
                ldsm_x4(al[im], (uint32_t)__cvta_generic_to_shared(&s.Al[mrow * SA + mcol]));
            }
            uint32_t bh[4][2], bl[4][2];
            #pragma unroll
            for (int g = 0; g < 2; g++) {
                int brow = ks + lrow;
                int bcol = wn * 32 + g * 16 + lcol8;
                uint32_t t[4];
                ldsm_x4_t(t, (uint32_t)__cvta_generic_to_shared(&s.Bh[brow * SB + bcol]));
                bh[2*g][0] = t[0]; bh[2*g][1] = t[1]; bh[2*g+1][0] = t[2]; bh[2*g+1][1] = t[3];
                ldsm_x4_t(t, (uint32_t)__cvta_generic_to_shared(&s.Bl[brow * SB + bcol]));
                bl[2*g][0] = t[0]; bl[2*g][1] = t[1]; bl[2*g+1][0] = t[2]; bl[2*g+1][1] = t[3];
            }
            #pragma unroll
            for (int im = 0; im < 2; im++)
                #pragma unroll
                for (int in = 0; in < 4; in++) {
                    mma_bf16(acc[im][in], ah[im], bh[in]);
                    mma_bf16(acc[im][in], ah[im], bl[in]);
                    mma_bf16(acc[im][in], al[im], bh[in]);
                }
        }
        __syncthreads();
    }

    // ---- epilogue ----
    #pragma unroll
    for (int im = 0; im < 2; im++) {
        int rbase = row0 + wm * 32 + im * 16 + (lane >> 2);
        #pragma unroll
        for (int in = 0; in < 4; in++) {
            int cc = col0 + wn * 32 + in * 8 + (lane & 3) * 2;
            float bs0 = bias[cc], bs1 = bias[cc + 1];
            #pragma unroll
            for (int half = 0; half < 2; half++) {
                int r = rbase + half * 8;
                if (r >= Mr) continue;
                float v0 = acc[im][in][half * 2 + 0] + bs0;
                float v1 = acc[im][in][half * 2 + 1] + bs1;
                if (act == 1) {
                    v0 = 0.5f * v0 * (1.f + erff(v0 * 0.70710678118654752f));
                    v1 = 0.5f * v1 * (1.f + erff(v1 * 0.70710678118654752f));
                }
                *(float2*)&C[(size_t)r * Nc + cc] = make_float2(v0, v1);
            }
        }
    }
}

__global__ __launch_bounds__(128)
void qkv_gemm_kernel(const float* __restrict__ x,
                     const float* __restrict__ Wq, const float* __restrict__ Wk,
                     const float* __restrict__ Wv,
                     const float* __restrict__ bq, const float* __restrict__ bk,
                     const float* __restrict__ bv,
                     float* __restrict__ q, float* __restrict__ k, float* __restrict__ v)
{
    const float* W; const float* b; float* o;
    if (blockIdx.z == 0)      { W = Wq; b = bq; o = q; }
    else if (blockIdx.z == 1) { W = Wk; b = bk; o = k; }
    else                      { W = Wv; b = bv; o = v; }
    gemm_core(x, W, b, o, TTOT, DDIM, DDIM, 0, blockIdx.y * 64, blockIdx.x * 64);
}

__global__ __launch_bounds__(128)
void ffn_gemm_kernel(const float* __restrict__ A, const float* __restrict__ B,
                     const float* __restrict__ bias, float* __restrict__ C,
                     int Mr, int K, int Nc, int act)
{
    gemm_core(A, B, bias, C, Mr, K, Nc, act, blockIdx.y * 64, blockIdx.x * 64);
}

// ================= attention: one warp per (token, head) =================
__global__ __launch_bounds__(128)
void attn_kernel(const float* __restrict__ q, const float* __restrict__ k,
                 const float* __restrict__ v, float* __restrict__ ctx)
{
    int t = blockIdx.x;
    int w = threadIdx.x >> 5;
    int lane = threadIdx.x & 31;
    int head = blockIdx.y * 4 + w;

    __shared__ float sc[4][264];
    __shared__ float qs[4][64];

    int b = (t < 8) ? (t >> 1) : ((t - 8) >> 8);
    const float scale = 0.125f;

    size_t qoff = (size_t)t * DDIM + head * 64;
    qs[w][lane]      = q[qoff + lane];
    qs[w][lane + 32] = q[qoff + lane + 32];
    __syncwarp();

    float mx = -1e30f;
    for (int j = lane; j < KKEYS; j += 32) {
        int key = (j < MMEM) ? (2 * b + j) : (8 + b * LSEQ + j - MMEM);
        const float4* kp = (const float4*)(k + (size_t)key * DDIM + head * 64);
        float d = 0.f;
        #pragma unroll
        for (int i = 0; i < 16; i++) {
            float4 kv = kp[i];
            d += kv.x * qs[w][4*i] + kv.y * qs[w][4*i+1]
               + kv.z * qs[w][4*i+2] + kv.w * qs[w][4*i+3];
        }
        d *= scale;
        sc[w][j] = d;
        mx = fmaxf(mx, d);
    }
    #pragma unroll
    for (int o = 16; o > 0; o >>= 1)
        mx = fmaxf(mx, __shfl_xor_sync(0xffffffffu, mx, o));

    float lsum = 0.f;
    for (int j = lane; j < KKEYS; j += 32) {
        float e = __expf(sc[w][j] - mx);
        sc[w][j] = e;
        lsum += e;
    }
    #pragma unroll
    for (int o = 16; o > 0; o >>= 1)
        lsum += __shfl_xor_sync(0xffffffffu, lsum, o);
    float inv = 1.f / lsum;
    __syncwarp();

    float a0 = 0.f, a1 = 0.f;
    for (int j = 0; j < KKEYS; j++) {
        int key = (j < MMEM) ? (2 * b + j) : (8 + b * LSEQ + j - MMEM);
        float p = sc[w][j];
        const float* vp = v + (size_t)key * DDIM + head * 64;
        a0 += p * vp[lane];
        a1 += p * vp[lane + 32];
    }
    ctx[qoff + lane]      = a0 * inv;
    ctx[qoff + lane + 32] = a1 * inv;
}

// ================= residual add + layernorm =================
__global__ __launch_bounds__(256)
void add_ln_kernel(float* __restrict__ x, const float* __restrict__ r,
                   const float* __restrict__ g, const float* __restrict__ b)
{
    int t = blockIdx.x;
    int tid = threadIdx.x;
    __shared__ float red[256];
    __shared__ float s_mu, s_rstd;

    float v[3];
    float lsum = 0.f;
    #pragma unroll
    for (int i = 0; i < 3; i++) {
        int d = tid + i * 256;
        v[i] = x[(size_t)t * DDIM + d] + r[(size_t)t * DDIM + d];
        lsum += v[i];
    }
    red[tid] = lsum;
    __syncthreads();
    for (int s = 128; s > 0; s >>= 1) {
        if (tid < s) red[tid] += red[tid + s];
        __syncthreads();
    }
    if (tid == 0) s_mu = red[0] * (1.f / DDIM);
    __syncthreads();
    float mu = s_mu;

    float lvar = 0.f;
    #pragma unroll
    for (int i = 0; i < 3; i++) {
        float d = v[i] - mu;
        lvar += d * d;
    }
    red[tid] = lvar;
    __syncthreads();
    for (int s = 128; s > 0; s >>= 1) {
        if (tid < s) red[tid] += red[tid + s];
        __syncthreads();
    }
    if (tid == 0) s_rstd = rsqrtf(red[0] * (1.f / DDIM) + 1e-5f);
    __syncthreads();
    float rstd = s_rstd;

    #pragma unroll
    for (int i = 0; i < 3; i++) {
        int d = tid + i * 256;
        x[(size_t)t * DDIM + d] = (v[i] - mu) * rstd * g[d] + b[d];
    }
}

// ================= output copy =================
__global__ void copy_out_kernel(const float* __restrict__ x, float* __restrict__ out)
{
    int idx = blockIdx.x * blockDim.x + threadIdx.x;
    if (idx < NB * LSEQ * DDIM)
        out[idx] = x[NB * MMEM * DDIM + idx];
}

extern "C" void kernel_launch(void* const* d_in, const int* in_sizes, int n_in,
                              void* d_out, int out_size)
{
    const int*   ids    = (const int*)  d_in[0];
    const float* memory = (const float*)d_in[1];
    const float* emb    = (const float*)d_in[2];
    const float* pos    = (const float*)d_in[3];
    const float* Wq     = (const float*)d_in[4];
    const float* bq     = (const float*)d_in[5];
    const float* Wk     = (const float*)d_in[6];
    const float* bk     = (const float*)d_in[7];
    const float* Wv     = (const float*)d_in[8];
    const float* bv     = (const float*)d_in[9];
    const float* W1     = (const float*)d_in[10];
    const float* b1     = (const float*)d_in[11];
    const float* W2     = (const float*)d_in[12];
    const float* b2     = (const float*)d_in[13];
    const float* g1     = (const float*)d_in[14];
    const float* be1    = (const float*)d_in[15];
    const float* g2     = (const float*)d_in[16];
    const float* be2    = (const float*)d_in[17];
    float* out = (float*)d_out;

    float *x, *q, *k, *v, *ctx, *h;
    cudaGetSymbolAddress((void**)&x,   g_x);
    cudaGetSymbolAddress((void**)&q,   g_q);
    cudaGetSymbolAddress((void**)&k,   g_k);
    cudaGetSymbolAddress((void**)&v,   g_v);
    cudaGetSymbolAddress((void**)&ctx, g_ctx);
    cudaGetSymbolAddress((void**)&h,   g_h);

    embed_kernel<<<(TTOT * DDIM + 255) / 256, 256>>>(ids, memory, emb, pos, x);

    const int MB = (TTOT + 63) / 64;   // 17
    dim3 grid_qkv(DDIM / 64, MB, 3);   // (12, 17, 3)
    dim3 grid_ff1(FFDIM / 64, MB);     // (48, 17)
    dim3 grid_ff2(DDIM / 64, MB);      // (12, 17)

    for (int i = 0; i < LAYERS; i++) {
        qkv_gemm_kernel<<<grid_qkv, 128>>>(
            x,
            Wq + (size_t)i * DDIM * DDIM, Wk + (size_t)i * DDIM * DDIM,
            Wv + (size_t)i * DDIM * DDIM,
            bq + i * DDIM, bk + i * DDIM, bv + i * DDIM,
            q, k, v);

        attn_kernel<<<dim3(TTOT, HNUM / 4), 128>>>(q, k, v, ctx);

        add_ln_kernel<<<TTOT, 256>>>(x, ctx, g1 + i * DDIM, be1 + i * DDIM);

        ffn_gemm_kernel<<<grid_ff1, 128>>>(x, W1 + (size_t)i * DDIM * FFDIM,
                                           b1 + i * FFDIM, h, TTOT, DDIM, FFDIM, 1);
        ffn_gemm_kernel<<<grid_ff2, 128>>>(h, W2 + (size_t)i * FFDIM * DDIM,
                                           b2 + i * DDIM, ctx, TTOT, FFDIM, DDIM, 0);

        add_ln_kernel<<<TTOT, 256>>>(x, ctx, g2 + i * DDIM, be2 + i * DDIM);
    }

    copy_out_kernel<<<(NB * LSEQ * DDIM + 255) / 256, 256>>>(x, out);
}

// round 7
// speedup vs baseline: 2.1990x; 1.1314x over previous
#include <cuda_runtime.h>
#include <cuda_bf16.h>
#include <math.h>
#include <stdint.h>

// Problem constants
#define NB 4
#define LSEQ 256
#define MMEM 2
#define DDIM 768
#define HNUM 12
#define FFDIM 3072
#define LAYERS 4
#define TTOT 1032
#define KKEYS 258

typedef __nv_bfloat16 bf16;

// -------- scratch (device globals) --------
__device__ float g_x[TTOT * DDIM];
__device__ float g_q[TTOT * DDIM];
__device__ float g_k[TTOT * DDIM];
__device__ float g_v[TTOT * DDIM];
__device__ float g_ctx[TTOT * DDIM];

__device__ bf16 g_xh[TTOT * DDIM];
__device__ bf16 g_xl[TTOT * DDIM];
__device__ bf16 g_hh[TTOT * FFDIM];
__device__ bf16 g_hl[TTOT * FFDIM];

// pre-split weights (bf16 hi/lo)
__device__ bf16 g_Wqh[LAYERS * DDIM * DDIM];
__device__ bf16 g_Wql[LAYERS * DDIM * DDIM];
__device__ bf16 g_Wkh[LAYERS * DDIM * DDIM];
__device__ bf16 g_Wkl[LAYERS * DDIM * DDIM];
__device__ bf16 g_Wvh[LAYERS * DDIM * DDIM];
__device__ bf16 g_Wvl[LAYERS * DDIM * DDIM];
__device__ bf16 g_W1h[LAYERS * DDIM * FFDIM];
__device__ bf16 g_W1l[LAYERS * DDIM * FFDIM];
__device__ bf16 g_W2h[LAYERS * DDIM * FFDIM];
__device__ bf16 g_W2l[LAYERS * DDIM * FFDIM];

// ================= helpers =================
__device__ __forceinline__ uint32_t packbf(bf16 a, bf16 b) {
    __nv_bfloat162 t = __nv_bfloat162(a, b);
    return *reinterpret_cast<uint32_t*>(&t);
}
__device__ __forceinline__ void split4(float4 v, uint2& hi, uint2& lo) {
    bf16 h0 = __float2bfloat16(v.x);
    bf16 h1 = __float2bfloat16(v.y);
    bf16 h2 = __float2bfloat16(v.z);
    bf16 h3 = __float2bfloat16(v.w);
    bf16 l0 = __float2bfloat16(v.x - __bfloat162float(h0));
    bf16 l1 = __float2bfloat16(v.y - __bfloat162float(h1));
    bf16 l2 = __float2bfloat16(v.z - __bfloat162float(h2));
    bf16 l3 = __float2bfloat16(v.w - __bfloat162float(h3));
    hi.x = packbf(h0, h1); hi.y = packbf(h2, h3);
    lo.x = packbf(l0, l1); lo.y = packbf(l2, l3);
}
__device__ __forceinline__ void split1(float v, bf16& h, bf16& l) {
    h = __float2bfloat16(v);
    l = __float2bfloat16(v - __bfloat162float(h));
}

__device__ __forceinline__ void ldsm_x4(uint32_t* r, uint32_t addr) {
    asm volatile("ldmatrix.sync.aligned.m8n8.x4.shared.b16 {%0,%1,%2,%3}, [%4];\n"
        : "=r"(r[0]), "=r"(r[1]), "=r"(r[2]), "=r"(r[3]) : "r"(addr));
}
__device__ __forceinline__ void ldsm_x4_t(uint32_t* r, uint32_t addr) {
    asm volatile("ldmatrix.sync.aligned.m8n8.x4.trans.shared.b16 {%0,%1,%2,%3}, [%4];\n"
        : "=r"(r[0]), "=r"(r[1]), "=r"(r[2]), "=r"(r[3]) : "r"(addr));
}
__device__ __forceinline__ void mma_bf16(float* c, const uint32_t* a, const uint32_t* b) {
    asm volatile("mma.sync.aligned.m16n8k16.row.col.f32.bf16.bf16.f32 "
        "{%0,%1,%2,%3}, {%4,%5,%6,%7}, {%8,%9}, {%0,%1,%2,%3};\n"
        : "+f"(c[0]), "+f"(c[1]), "+f"(c[2]), "+f"(c[3])
        : "r"(a[0]), "r"(a[1]), "r"(a[2]), "r"(a[3]), "r"(b[0]), "r"(b[1]));
}
__device__ __forceinline__ void cpa16(void* dst, const void* src, int sz) {
    uint32_t d = (uint32_t)__cvta_generic_to_shared(dst);
    asm volatile("cp.async.cg.shared.global [%0], [%1], 16, %2;\n"
        :: "r"(d), "l"(src), "r"(sz));
}
__device__ __forceinline__ void cp_commit() {
    asm volatile("cp.async.commit_group;\n");
}
template<int N>
__device__ __forceinline__ void cp_wait() {
    asm volatile("cp.async.wait_group %0;\n" :: "n"(N));
}

// smem XOR swizzles (conflict-free for ldmatrix, 16B-aligned for cp.async)
__device__ __forceinline__ int swzA(int row, int col) {   // 32 cols
    int chunk = (col >> 3) ^ ((row >> 1) & 3);
    return row * 32 + chunk * 8;
}
__device__ __forceinline__ int swzB(int row, int col) {   // 64 cols
    int chunk = (col >> 3) ^ (row & 7);
    return row * 64 + chunk * 8;
}

// ================= weight conversion =================
__global__ void convw_kernel(const float4* __restrict__ src,
                             bf16* __restrict__ h, bf16* __restrict__ l, int n4)
{
    int idx = blockIdx.x * blockDim.x + threadIdx.x;
    if (idx >= n4) return;
    float4 v = src[idx];
    uint2 hi, lo;
    split4(v, hi, lo);
    *(uint2*)&h[idx * 4] = hi;
    *(uint2*)&l[idx * 4] = lo;
}

// ================= embedding (fp32 + bf16 split) =================
__global__ void embed_kernel(const int* __restrict__ ids,
                             const float* __restrict__ memory,
                             const float* __restrict__ emb,
                             const float* __restrict__ pos,
                             float* __restrict__ x,
                             bf16* __restrict__ xh, bf16* __restrict__ xl)
{
    int idx = blockIdx.x * blockDim.x + threadIdx.x;
    if (idx >= TTOT * DDIM) return;
    int t = idx / DDIM;
    int d = idx - t * DDIM;
    float val;
    if (t < NB * MMEM) {
        val = memory[idx] + pos[(t & 1) * DDIM + d];
    } else {
        int tt = t - NB * MMEM;
        int tok = ids[tt];
        val = emb[(size_t)tok * DDIM + d] + pos[(MMEM + (tt & (LSEQ - 1))) * DDIM + d];
    }
    x[idx] = val;
    bf16 h, l;
    split1(val, h, l);
    xh[idx] = h; xl[idx] = l;
}

// ================= pipelined bf16x3 GEMM =================
// BM=128, BN=64, BK=32; 256 threads = 8 warps (4m x 2n), warptile 32x32.
// ACT=0: C fp32 (+bias). ACT=1: gelu(.)->split bf16 into Ch/Cl.

struct __align__(16) SmemGemm {
    bf16 Ah[2][128 * 32];
    bf16 Al[2][128 * 32];
    bf16 Bh[2][32 * 64];
    bf16 Bl[2][32 * 64];
};

template<int ACT>
__device__ __forceinline__ void gemm_core(
    const bf16* __restrict__ Agh, const bf16* __restrict__ Agl,
    const bf16* __restrict__ Bgh, const bf16* __restrict__ Bgl,
    const float* __restrict__ bias,
    float* __restrict__ C, bf16* __restrict__ Ch, bf16* __restrict__ Cl,
    int Mr, int K, int Nc, int row0, int col0)
{
    __shared__ SmemGemm s;

    int tid = threadIdx.x;
    int lane = tid & 31;
    int wid = tid >> 5;
    int wm = wid & 3;           // 0..3
    int wn = wid >> 2;          // 0..1
    int lrow = lane & 15;
    int lcol8 = (lane >> 4) * 8;

    float acc[2][4][4];
    #pragma unroll
    for (int im = 0; im < 2; im++)
        #pragma unroll
        for (int in = 0; in < 4; in++)
            #pragma unroll
            for (int r = 0; r < 4; r++) acc[im][in][r] = 0.f;

    int arow = tid >> 2;          // 0..63
    int acol = (tid & 3) * 8;     // 0,8,16,24
    int brow = tid >> 3;          // 0..31
    int bcol = (tid & 7) * 8;     // 0..56

    // ---- stage loader ----
    auto load_stage = [&](int st, int k0) {
        #pragma unroll
        for (int i = 0; i < 2; i++) {
            int row = arow + i * 64;
            int grow = row0 + row;
            int ok = (grow < Mr) ? 16 : 0;
            int gr = (grow < Mr) ? grow : 0;
            const bf16* sh = &Agh[(size_t)gr * K + k0 + acol];
            const bf16* sl = &Agl[(size_t)gr * K + k0 + acol];
            cpa16(&s.Ah[st][swzA(row, acol)], sh, ok);
            cpa16(&s.Al[st][swzA(row, acol)], sl, ok);
        }
        cpa16(&s.Bh[st][swzB(brow, bcol)], &Bgh[(size_t)(k0 + brow) * Nc + col0 + bcol], 16);
        cpa16(&s.Bl[st][swzB(brow, bcol)], &Bgl[(size_t)(k0 + brow) * Nc + col0 + bcol], 16);
        cp_commit();
    };

    int nit = K / 32;
    load_stage(0, 0);

    for (int iter = 0; iter < nit; iter++) {
        int st = iter & 1;
        if (iter + 1 < nit) {
            load_stage(st ^ 1, (iter + 1) * 32);
            cp_wait<1>();
        } else {
            cp_wait<0>();
        }
        __syncthreads();

        #pragma unroll
        for (int ks = 0; ks < 32; ks += 16) {
            uint32_t ah[2][4], al[2][4];
            #pragma unroll
            for (int im = 0; im < 2; im++) {
                int mrow = wm * 32 + im * 16 + lrow;
                int mcol = ks + lcol8;
                ldsm_x4(ah[im], (uint32_t)__cvta_generic_to_shared(&s.Ah[st][swzA(mrow, mcol)]));
                ldsm_x4(al[im], (uint32_t)__cvta_generic_to_shared(&s.Al[st][swzA(mrow, mcol)]));
            }
            uint32_t bh[4][2], bl[4][2];
            #pragma unroll
            for (int g = 0; g < 2; g++) {
                int br = ks + lrow;
                int bc = wn * 32 + g * 16 + lcol8;
                uint32_t t[4];
                ldsm_x4_t(t, (uint32_t)__cvta_generic_to_shared(&s.Bh[st][swzB(br, bc)]));
                bh[2*g][0] = t[0]; bh[2*g][1] = t[1]; bh[2*g+1][0] = t[2]; bh[2*g+1][1] = t[3];
                ldsm_x4_t(t, (uint32_t)__cvta_generic_to_shared(&s.Bl[st][swzB(br, bc)]));
                bl[2*g][0] = t[0]; bl[2*g][1] = t[1]; bl[2*g+1][0] = t[2]; bl[2*g+1][1] = t[3];
            }
            #pragma unroll
            for (int im = 0; im < 2; im++)
                #pragma unroll
                for (int in = 0; in < 4; in++) {
                    mma_bf16(acc[im][in], ah[im], bh[in]);
                    mma_bf16(acc[im][in], ah[im], bl[in]);
                    mma_bf16(acc[im][in], al[im], bh[in]);
                }
        }
        __syncthreads();
    }

    // ---- epilogue ----
    #pragma unroll
    for (int im = 0; im < 2; im++) {
        int rbase = row0 + wm * 32 + im * 16 + (lane >> 2);
        #pragma unroll
        for (int in = 0; in < 4; in++) {
            int cc = col0 + wn * 32 + in * 8 + (lane & 3) * 2;
            float bs0 = bias[cc], bs1 = bias[cc + 1];
            #pragma unroll
            for (int half = 0; half < 2; half++) {
                int r = rbase + half * 8;
                if (r >= Mr) continue;
                float v0 = acc[im][in][half * 2 + 0] + bs0;
                float v1 = acc[im][in][half * 2 + 1] + bs1;
                if (ACT == 1) {
                    v0 = 0.5f * v0 * (1.f + erff(v0 * 0.70710678118654752f));
                    v1 = 0.5f * v1 * (1.f + erff(v1 * 0.70710678118654752f));
                    bf16 h0, l0, h1, l1;
                    split1(v0, h0, l0); split1(v1, h1, l1);
                    *(uint32_t*)&Ch[(size_t)r * Nc + cc] = packbf(h0, h1);
                    *(uint32_t*)&Cl[(size_t)r * Nc + cc] = packbf(l0, l1);
                } else {
                    *(float2*)&C[(size_t)r * Nc + cc] = make_float2(v0, v1);
                }
            }
        }
    }
}

__global__ __launch_bounds__(256)
void qkv_gemm_kernel(const bf16* __restrict__ xh, const bf16* __restrict__ xl,
                     const bf16* __restrict__ Wqh, const bf16* __restrict__ Wql,
                     const bf16* __restrict__ Wkh, const bf16* __restrict__ Wkl,
                     const bf16* __restrict__ Wvh, const bf16* __restrict__ Wvl,
                     const float* __restrict__ bq, const float* __restrict__ bk,
                     const float* __restrict__ bv,
                     float* __restrict__ q, float* __restrict__ k, float* __restrict__ v)
{
    const bf16 *Wh, *Wl; const float* b; float* o;
    if (blockIdx.z == 0)      { Wh = Wqh; Wl = Wql; b = bq; o = q; }
    else if (blockIdx.z == 1) { Wh = Wkh; Wl = Wkl; b = bk; o = k; }
    else                      { Wh = Wvh; Wl = Wvl; b = bv; o = v; }
    gemm_core<0>(xh, xl, Wh, Wl, b, o, nullptr, nullptr,
                 TTOT, DDIM, DDIM, blockIdx.y * 128, blockIdx.x * 64);
}

__global__ __launch_bounds__(256)
void ff1_gemm_kernel(const bf16* __restrict__ xh, const bf16* __restrict__ xl,
                     const bf16* __restrict__ W1h, const bf16* __restrict__ W1l,
                     const float* __restrict__ b1,
                     bf16* __restrict__ hh, bf16* __restrict__ hl)
{
    gemm_core<1>(xh, xl, W1h, W1l, b1, nullptr, hh, hl,
                 TTOT, DDIM, FFDIM, blockIdx.y * 128, blockIdx.x * 64);
}

__global__ __launch_bounds__(256)
void ff2_gemm_kernel(const bf16* __restrict__ hh, const bf16* __restrict__ hl,
                     const bf16* __restrict__ W2h, const bf16* __restrict__ W2l,
                     const float* __restrict__ b2, float* __restrict__ ctx)
{
    gemm_core<0>(hh, hl, W2h, W2l, b2, ctx, nullptr, nullptr,
                 TTOT, FFDIM, DDIM, blockIdx.y * 128, blockIdx.x * 64);
}

// ================= attention: one warp per (token, head) =================
__global__ __launch_bounds__(128)
void attn_kernel(const float* __restrict__ q, const float* __restrict__ k,
                 const float* __restrict__ v, float* __restrict__ ctx)
{
    int t = blockIdx.x;
    int w = threadIdx.x >> 5;
    int lane = threadIdx.x & 31;
    int head = blockIdx.y * 4 + w;

    __shared__ float sc[4][264];
    __shared__ float qs[4][64];

    int b = (t < 8) ? (t >> 1) : ((t - 8) >> 8);
    const float scale = 0.125f;

    size_t qoff = (size_t)t * DDIM + head * 64;
    qs[w][lane]      = q[qoff + lane];
    qs[w][lane + 32] = q[qoff + lane + 32];
    __syncwarp();

    float mx = -1e30f;
    for (int j = lane; j < KKEYS; j += 32) {
        int key = (j < MMEM) ? (2 * b + j) : (8 + b * LSEQ + j - MMEM);
        const float4* kp = (const float4*)(k + (size_t)key * DDIM + head * 64);
        float d = 0.f;
        #pragma unroll
        for (int i = 0; i < 16; i++) {
            float4 kv = kp[i];
            d += kv.x * qs[w][4*i] + kv.y * qs[w][4*i+1]
               + kv.z * qs[w][4*i+2] + kv.w * qs[w][4*i+3];
        }
        d *= scale;
        sc[w][j] = d;
        mx = fmaxf(mx, d);
    }
    #pragma unroll
    for (int o = 16; o > 0; o >>= 1)
        mx = fmaxf(mx, __shfl_xor_sync(0xffffffffu, mx, o));

    float lsum = 0.f;
    for (int j = lane; j < KKEYS; j += 32) {
        float e = __expf(sc[w][j] - mx);
        sc[w][j] = e;
        lsum += e;
    }
    #pragma unroll
    for (int o = 16; o > 0; o >>= 1)
        lsum += __shfl_xor_sync(0xffffffffu, lsum, o);
    float inv = 1.f / lsum;
    __syncwarp();

    float a0 = 0.f, a1 = 0.f;
    for (int j = 0; j < KKEYS; j++) {
        int key = (j < MMEM) ? (2 * b + j) : (8 + b * LSEQ + j - MMEM);
        float p = sc[w][j];
        const float* vp = v + (size_t)key * DDIM + head * 64;
        a0 += p * vp[lane];
        a1 += p * vp[lane + 32];
    }
    ctx[qoff + lane]      = a0 * inv;
    ctx[qoff + lane + 32] = a1 * inv;
}

// ================= residual add + LN (warp per token, shuffle-only) =================
__global__ __launch_bounds__(256)
void add_ln_kernel(float* __restrict__ x, const float* __restrict__ r,
                   const float* __restrict__ g, const float* __restrict__ b,
                   bf16* __restrict__ xh, bf16* __restrict__ xl)
{
    int wid = threadIdx.x >> 5;
    int lane = threadIdx.x & 31;
    int t = blockIdx.x * 8 + wid;
    if (t >= TTOT) return;

    const float4* xp = (const float4*)(x + (size_t)t * DDIM);
    const float4* rp = (const float4*)(r + (size_t)t * DDIM);
    const float4* gp = (const float4*)g;
    const float4* bp = (const float4*)b;

    float4 v[6];
    float sum = 0.f;
    #pragma unroll
    for (int i = 0; i < 6; i++) {
        int idx = lane + i * 32;
        float4 a = xp[idx], c = rp[idx];
        v[i] = make_float4(a.x + c.x, a.y + c.y, a.z + c.z, a.w + c.w);
        sum += v[i].x + v[i].y + v[i].z + v[i].w;
    }
    #pragma unroll
    for (int o = 16; o > 0; o >>= 1) sum += __shfl_xor_sync(0xffffffffu, sum, o);
    float mu = sum * (1.f / DDIM);

    float var = 0.f;
    #pragma unroll
    for (int i = 0; i < 6; i++) {
        float dx = v[i].x - mu, dy = v[i].y - mu, dz = v[i].z - mu, dw = v[i].w - mu;
        var += dx * dx + dy * dy + dz * dz + dw * dw;
    }
    #pragma unroll
    for (int o = 16; o > 0; o >>= 1) var += __shfl_xor_sync(0xffffffffu, var, o);
    float rstd = rsqrtf(var * (1.f / DDIM) + 1e-5f);

    float4* xo = (float4*)(x + (size_t)t * DDIM);
    #pragma unroll
    for (int i = 0; i < 6; i++) {
        int idx = lane + i * 32;
        float4 gg = gp[idx], bb = bp[idx];
        float4 o;
        o.x = (v[i].x - mu) * rstd * gg.x + bb.x;
        o.y = (v[i].y - mu) * rstd * gg.y + bb.y;
        o.z = (v[i].z - mu) * rstd * gg.z + bb.z;
        o.w = (v[i].w - mu) * rstd * gg.w + bb.w;
        xo[idx] = o;
        uint2 hi, lo;
        split4(o, hi, lo);
        *(uint2*)&xh[(size_t)t * DDIM + idx * 4] = hi;
        *(uint2*)&xl[(size_t)t * DDIM + idx * 4] = lo;
    }
}

// ================= output copy =================
__global__ void copy_out_kernel(const float* __restrict__ x, float* __restrict__ out)
{
    int idx = blockIdx.x * blockDim.x + threadIdx.x;
    if (idx < NB * LSEQ * DDIM)
        out[idx] = x[NB * MMEM * DDIM + idx];
}

extern "C" void kernel_launch(void* const* d_in, const int* in_sizes, int n_in,
                              void* d_out, int out_size)
{
    const int*   ids    = (const int*)  d_in[0];
    const float* memory = (const float*)d_in[1];
    const float* emb    = (const float*)d_in[2];
    const float* pos    = (const float*)d_in[3];
    const float* Wq     = (const float*)d_in[4];
    const float* bq     = (const float*)d_in[5];
    const float* Wk     = (const float*)d_in[6];
    const float* bk     = (const float*)d_in[7];
    const float* Wv     = (const float*)d_in[8];
    const float* bv     = (const float*)d_in[9];
    const float* W1     = (const float*)d_in[10];
    const float* b1     = (const float*)d_in[11];
    const float* W2     = (const float*)d_in[12];
    const float* b2     = (const float*)d_in[13];
    const float* g1     = (const float*)d_in[14];
    const float* be1    = (const float*)d_in[15];
    const float* g2     = (const float*)d_in[16];
    const float* be2    = (const float*)d_in[17];
    float* out = (float*)d_out;

    float *x, *q, *k, *v, *ctx;
    bf16 *xh, *xl, *hh, *hl;
    bf16 *Wqh, *Wql, *Wkh, *Wkl, *Wvh, *Wvl, *W1h, *W1l, *W2h, *W2l;
    cudaGetSymbolAddress((void**)&x,   g_x);
    cudaGetSymbolAddress((void**)&q,   g_q);
    cudaGetSymbolAddress((void**)&k,   g_k);
    cudaGetSymbolAddress((void**)&v,   g_v);
    cudaGetSymbolAddress((void**)&ctx, g_ctx);
    cudaGetSymbolAddress((void**)&xh,  g_xh);
    cudaGetSymbolAddress((void**)&xl,  g_xl);
    cudaGetSymbolAddress((void**)&hh,  g_hh);
    cudaGetSymbolAddress((void**)&hl,  g_hl);
    cudaGetSymbolAddress((void**)&Wqh, g_Wqh);
    cudaGetSymbolAddress((void**)&Wql, g_Wql);
    cudaGetSymbolAddress((void**)&Wkh, g_Wkh);
    cudaGetSymbolAddress((void**)&Wkl, g_Wkl);
    cudaGetSymbolAddress((void**)&Wvh, g_Wvh);
    cudaGetSymbolAddress((void**)&Wvl, g_Wvl);
    cudaGetSymbolAddress((void**)&W1h, g_W1h);
    cudaGetSymbolAddress((void**)&W1l, g_W1l);
    cudaGetSymbolAddress((void**)&W2h, g_W2h);
    cudaGetSymbolAddress((void**)&W2l, g_W2l);

    // ---- pre-split weights ----
    {
        int nqkv4 = LAYERS * DDIM * DDIM / 4;       // 589824
        int nff4  = LAYERS * DDIM * FFDIM / 4;      // 2359296
        convw_kernel<<<(nqkv4 + 255) / 256, 256>>>((const float4*)Wq, Wqh, Wql, nqkv4);
        convw_kernel<<<(nqkv4 + 255) / 256, 256>>>((const float4*)Wk, Wkh, Wkl, nqkv4);
        convw_kernel<<<(nqkv4 + 255) / 256, 256>>>((const float4*)Wv, Wvh, Wvl, nqkv4);
        convw_kernel<<<(nff4  + 255) / 256, 256>>>((const float4*)W1, W1h, W1l, nff4);
        convw_kernel<<<(nff4  + 255) / 256, 256>>>((const float4*)W2, W2h, W2l, nff4);
    }

    embed_kernel<<<(TTOT * DDIM + 255) / 256, 256>>>(ids, memory, emb, pos, x, xh, xl);

    const int MB = (TTOT + 127) / 128;  // 9
    dim3 grid_qkv(DDIM / 64, MB, 3);    // (12, 9, 3)
    dim3 grid_ff1(FFDIM / 64, MB);      // (48, 9)
    dim3 grid_ff2(DDIM / 64, MB);       // (12, 9)
    int ln_grid = (TTOT + 7) / 8;       // 129

    for (int i = 0; i < LAYERS; i++) {
        size_t od = (size_t)i * DDIM * DDIM;
        size_t of = (size_t)i * DDIM * FFDIM;
        qkv_gemm_kernel<<<grid_qkv, 256>>>(
            xh, xl,
            Wqh + od, Wql + od, Wkh + od, Wkl + od, Wvh + od, Wvl + od,
            bq + i * DDIM, bk + i * DDIM, bv + i * DDIM,
            q, k, v);

        attn_kernel<<<dim3(TTOT, HNUM / 4), 128>>>(q, k, v, ctx);

        add_ln_kernel<<<ln_grid, 256>>>(x, ctx, g1 + i * DDIM, be1 + i * DDIM, xh, xl);

        ff1_gemm_kernel<<<grid_ff1, 256>>>(xh, xl, W1h + of, W1l + of,
                                           b1 + i * FFDIM, hh, hl);
        ff2_gemm_kernel<<<grid_ff2, 256>>>(hh, hl, W2h + of, W2l + of,
                                           b2 + i * DDIM, ctx);

        add_ln_kernel<<<ln_grid, 256>>>(x, ctx, g2 + i * DDIM, be2 + i * DDIM, xh, xl);
    }

    copy_out_kernel<<<(NB * LSEQ * DDIM + 255) / 256, 256>>>(x, out);
}